// round 5
// baseline (speedup 1.0000x reference)
#include <cuda_runtime.h>
#include <cstdint>

// CMPModel density matrix via warp-level mma.sync tf32, sm_103.
// V=50000, D=256, S=128, B=64.
//
// R[k,d]=word_emb[q[k],d], I[k,d]=cmp_emb[q[k],d]*pos[k]
//   real[d,e] = sum_k w[k]( R[k,d]R[k,e] + I[k,d]I[k,e] )   (SYMMETRIC)
//   imag[d,e] = sum_k w[k]( I[k,d]R[k,e] - R[k,d]I[k,e] )   (ANTISYMMETRIC)
//
// Symmetry: only tiles (dt,et) in {(0,0),(0,1),(1,1)} are computed (192 CTAs);
// the (1,0) block is the (anti)transpose of (0,1), written via an SMEM
// transpose by the (0,1) CTAs.
// MMA issue order is pass-major so same-accumulator RAW distance is 4.

#define D_DIM 256
#define S_LEN 128
#define B_DIM 64
#define KC    32
#define PAD   136

#define TILE_FLOATS (KC * PAD)              // 4352
#define STAGE_FLOATS (4 * TILE_FLOATS)      // AR, AI, BR, BI
#define SMEM_FLOATS (2 * STAGE_FLOATS)
#define SMEM_BYTES  (SMEM_FLOATS * 4)       // 139264 B
#define TPITCH 132                          // transpose staging pitch (floats)

__device__ __forceinline__ uint32_t tf32r(float f) {
    uint32_t r;
    asm("cvt.rna.tf32.f32 %0, %1;" : "=r"(r) : "f"(f));
    return r;
}

// NOT volatile: pure register op; lets ptxas schedule across MMAs.
__device__ __forceinline__ void mma8(float* c, const uint32_t* a, const uint32_t* b) {
    asm("mma.sync.aligned.m16n8k8.row.col.f32.tf32.tf32.f32 "
        "{%0,%1,%2,%3}, {%4,%5,%6,%7}, {%8,%9}, {%0,%1,%2,%3};"
        : "+f"(c[0]), "+f"(c[1]), "+f"(c[2]), "+f"(c[3])
        : "r"(a[0]), "r"(a[1]), "r"(a[2]), "r"(a[3]), "r"(b[0]), "r"(b[1]));
}

__global__ void __launch_bounds__(512, 1)
cmp_mma3_kernel(const int*   __restrict__ questions,
                const float* __restrict__ qpos,
                const float* __restrict__ wemb,
                const float* __restrict__ cemb,
                const float* __restrict__ wq,
                float*       __restrict__ out)
{
    extern __shared__ float sm[];
    __shared__ int   sq[S_LEN];
    __shared__ float sp[S_LEN];
    __shared__ float sw[S_LEN];

    const int tid  = threadIdx.x;
    const int wid  = tid >> 5;
    const int lane = tid & 31;
    const int tile = blockIdx.x;           // 0:(0,0) 1:(0,1)+mirror 2:(1,1)
    const int b    = blockIdx.y;
    const int dt   = (tile == 2) ? 1 : 0;
    const int et   = (tile >= 1) ? 1 : 0;

    if (tid < S_LEN) {
        sq[tid] = questions[b * S_LEN + tid];
        sp[tid] = qpos[b * S_LEN + tid];
        sw[tid] = wq[tid];
    }
    __syncthreads();

    const int mr = wid >> 2;       // d block (32 rows)
    const int nc = wid & 3;        // e block (32 cols)

    float accRe[2][4][4];
    float accIm[2][4][4];
#pragma unroll
    for (int i = 0; i < 2; i++)
#pragma unroll
        for (int j = 0; j < 4; j++)
#pragma unroll
            for (int q = 0; q < 4; q++) { accRe[i][j][q] = 0.f; accIm[i][j][q] = 0.f; }

    const int f4l = lane & 7;
    const int k4  = lane >> 3;
    const int r = lane >> 2;
    const int c = lane & 3;

    auto gather = [&](int g) {
        float* stage = sm + (g & 1) * STAGE_FLOATS;
        float* AR = stage;
        float* AI = stage + 1 * TILE_FLOATS;
        float* BR = stage + 2 * TILE_FLOATS;
        float* BI = stage + 3 * TILE_FLOATS;
#pragma unroll
        for (int i = 0; i < 4; ++i) {
            const int witer = wid + 16 * i;
            const int half  = witer >> 5;
            const int u     = witer & 31;
            const int k     = (u & 7) * 4 + k4;
            const int f4    = (u >> 3) * 8 + f4l;

            const int   s  = g * KC + k;
            const int   q  = sq[s];
            const float pp = sp[s];
            const int   fofs = (half ? et : dt) * 128 + f4 * 4;
            const float4 rv = *(const float4*)(wemb + (size_t)q * D_DIM + fofs);
            const float4 cv = *(const float4*)(cemb + (size_t)q * D_DIM + fofs);
            const float ix = cv.x * pp, iy = cv.y * pp, iz = cv.z * pp, iw = cv.w * pp;
            const int dst = k * PAD + f4 * 4;

            if (half == 0) {
                *(uint4*)(AR + dst) = make_uint4(tf32r(rv.x), tf32r(rv.y),
                                                 tf32r(rv.z), tf32r(rv.w));
                *(uint4*)(AI + dst) = make_uint4(tf32r(ix), tf32r(iy),
                                                 tf32r(iz), tf32r(iw));
            } else {
                const float ww = sw[s];
                *(uint4*)(BR + dst) = make_uint4(tf32r(rv.x * ww), tf32r(rv.y * ww),
                                                 tf32r(rv.z * ww), tf32r(rv.w * ww));
                *(uint4*)(BI + dst) = make_uint4(tf32r(ix * ww), tf32r(iy * ww),
                                                 tf32r(iz * ww), tf32r(iw * ww));
            }
        }
    };

    gather(0);
    __syncthreads();

    for (int g = 0; g < 4; ++g) {
        float* stage = sm + (g & 1) * STAGE_FLOATS;
        const float* AR = stage;
        const float* AI = stage + 1 * TILE_FLOATS;
        const float* BR = stage + 2 * TILE_FLOATS;
        const float* BI = stage + 3 * TILE_FLOATS;

        if (g < 3) gather(g + 1);

#pragma unroll
        for (int ks = 0; ks < 4; ++ks) {
            const int k0 = ks * 8;
            const int rowL = (k0 + c) * PAD;
            const int rowH = (k0 + 4 + c) * PAD;

            uint32_t bR[4][2], bI[4][2], bN[4][2];
#pragma unroll
            for (int nt = 0; nt < 4; ++nt) {
                const int n0 = nc * 32 + nt * 8 + r;
                bR[nt][0] = __float_as_uint(BR[rowL + n0]);
                bR[nt][1] = __float_as_uint(BR[rowH + n0]);
                bI[nt][0] = __float_as_uint(BI[rowL + n0]);
                bI[nt][1] = __float_as_uint(BI[rowH + n0]);
                bN[nt][0] = bI[nt][0] ^ 0x80000000u;
                bN[nt][1] = bI[nt][1] ^ 0x80000000u;
            }
#pragma unroll
            for (int mt = 0; mt < 2; ++mt) {
                const int m0 = mr * 32 + mt * 16 + r;
                uint32_t aR[4], aI[4];
                aR[0] = __float_as_uint(AR[rowL + m0]);
                aR[1] = __float_as_uint(AR[rowL + m0 + 8]);
                aR[2] = __float_as_uint(AR[rowH + m0]);
                aR[3] = __float_as_uint(AR[rowH + m0 + 8]);
                aI[0] = __float_as_uint(AI[rowL + m0]);
                aI[1] = __float_as_uint(AI[rowL + m0 + 8]);
                aI[2] = __float_as_uint(AI[rowH + m0]);
                aI[3] = __float_as_uint(AI[rowH + m0 + 8]);
                // pass-major: same-accumulator RAW distance = 4
#pragma unroll
                for (int nt = 0; nt < 4; ++nt) mma8(accRe[mt][nt], aR, bR[nt]);
#pragma unroll
                for (int nt = 0; nt < 4; ++nt) mma8(accRe[mt][nt], aI, bI[nt]);
#pragma unroll
                for (int nt = 0; nt < 4; ++nt) mma8(accIm[mt][nt], aI, bR[nt]);
#pragma unroll
                for (int nt = 0; nt < 4; ++nt) mma8(accIm[mt][nt], aR, bN[nt]);
            }
        }
        __syncthreads();
    }

    // ---- epilogue: direct block ----
    float* oRe = out + (size_t)b * D_DIM * D_DIM;
    float* oIm = oRe + (size_t)B_DIM * D_DIM * D_DIM;
#pragma unroll
    for (int mt = 0; mt < 2; ++mt) {
        const int d = dt * 128 + mr * 32 + mt * 16 + r;
#pragma unroll
        for (int nt = 0; nt < 4; ++nt) {
            const int e = et * 128 + nc * 32 + nt * 8 + 2 * c;
            *(float2*)(oRe + (size_t)d * D_DIM + e) =
                make_float2(accRe[mt][nt][0], accRe[mt][nt][1]);
            *(float2*)(oRe + (size_t)(d + 8) * D_DIM + e) =
                make_float2(accRe[mt][nt][2], accRe[mt][nt][3]);
            *(float2*)(oIm + (size_t)d * D_DIM + e) =
                make_float2(accIm[mt][nt][0], accIm[mt][nt][1]);
            *(float2*)(oIm + (size_t)(d + 8) * D_DIM + e) =
                make_float2(accIm[mt][nt][2], accIm[mt][nt][3]);
        }
    }

    // ---- mirror block for tile (0,1): out[(1,0)] via SMEM transpose ----
    if (tile == 1) {
        float* T = sm;   // reuse stage 0 (all compute synced)
        // rows of T indexed by e_local, cols by d_local, pitch TPITCH
#pragma unroll
        for (int mat = 0; mat < 2; ++mat) {
            __syncthreads();
            // write acc -> T[e_local][d_local] (scalar STS, banks verified)
#pragma unroll
            for (int mt = 0; mt < 2; ++mt) {
                const int dl = mr * 32 + mt * 16 + r;
#pragma unroll
                for (int nt = 0; nt < 4; ++nt) {
                    const int el = nc * 32 + nt * 8 + 2 * c;
                    const float* a = mat ? accIm[mt][nt] : accRe[mt][nt];
                    T[(size_t)el * TPITCH + dl]           = a[0];
                    T[(size_t)(el + 1) * TPITCH + dl]     = a[1];
                    T[(size_t)el * TPITCH + dl + 8]       = a[2];
                    T[(size_t)(el + 1) * TPITCH + dl + 8] = a[3];
                }
            }
            __syncthreads();
            // read rows of T coalesced, store to mirrored block
            // mirror: dest row d' = 128 + e_local, dest col e' = d_local
            float* ob = mat ? oIm : oRe;
            const float sgn = mat ? -1.f : 1.f;
#pragma unroll
            for (int rr = 0; rr < 8; ++rr) {
                const int el = rr * 16 + wid;
                float4 v = *(const float4*)(T + (size_t)el * TPITCH + lane * 4);
                v.x *= sgn; v.y *= sgn; v.z *= sgn; v.w *= sgn;
                *(float4*)(ob + (size_t)(128 + el) * D_DIM + lane * 4) = v;
            }
        }
    }
}

extern "C" void kernel_launch(void* const* d_in, const int* in_sizes, int n_in,
                              void* d_out, int out_size) {
    const int*   questions = (const int*)d_in[0];
    const float* qpos      = (const float*)d_in[1];
    const float* wemb      = (const float*)d_in[2];
    const float* cemb      = (const float*)d_in[3];
    const float* wq        = (const float*)d_in[4];
    float*       out       = (float*)d_out;

    cudaFuncSetAttribute(cmp_mma3_kernel,
                         cudaFuncAttributeMaxDynamicSharedMemorySize, SMEM_BYTES);

    dim3 grid(3 /*tiles*/, B_DIM);
    cmp_mma3_kernel<<<grid, 512, SMEM_BYTES>>>(questions, qpos, wemb, cemb, wq, out);
}

// round 6
// speedup vs baseline: 1.1120x; 1.1120x over previous
#include <cuda_runtime.h>
#include <cstdint>

// CMPModel density matrix via warp-level mma.sync tf32, sm_103.
// V=50000, D=256, S=128, B=64.
//
// R[k,d]=word_emb[q[k],d], I[k,d]=cmp_emb[q[k],d]*pos[k]
//   real[d,e] = sum_k w[k]( R[k,d]R[k,e] + I[k,d]I[k,e] )   (SYMMETRIC)
//   imag[d,e] = sum_k w[k]( I[k,d]R[k,e] - R[k,d]I[k,e] )   (ANTISYMMETRIC)
//
// 6 subtiles per batch (128d x 64e each), skipping the (1,0) quarter which is
// the (anti)transpose of (0,1).  384 CTAs, 256 threads, 2 CTAs/SM.
//   st 0..3: dt=0, e0=st*64         (st 2,3 also write mirrored block)
//   st 4..5: dt=1, e0=128+(st-4)*64

#define D_DIM 256
#define S_LEN 128
#define B_DIM 64
#define KC    32
#define APAD  136                 // A tiles pitch (128 data)
#define BPAD  72                  // B tiles pitch (64 data)

#define A_TILE (KC * APAD)        // 4352 floats
#define B_TILE (KC * BPAD)        // 2304 floats
#define STAGE_FLOATS (2 * A_TILE + 2 * B_TILE)   // 13312
#define SMEM_FLOATS (2 * STAGE_FLOATS)
#define SMEM_BYTES  (SMEM_FLOATS * 4)            // 106496 B
#define TPITCH 132                // mirror transpose pitch

__device__ __forceinline__ uint32_t tf32r(float f) {
    uint32_t r;
    asm("cvt.rna.tf32.f32 %0, %1;" : "=r"(r) : "f"(f));
    return r;
}

__device__ __forceinline__ void mma8(float* c, const uint32_t* a, const uint32_t* b) {
    asm("mma.sync.aligned.m16n8k8.row.col.f32.tf32.tf32.f32 "
        "{%0,%1,%2,%3}, {%4,%5,%6,%7}, {%8,%9}, {%0,%1,%2,%3};"
        : "+f"(c[0]), "+f"(c[1]), "+f"(c[2]), "+f"(c[3])
        : "r"(a[0]), "r"(a[1]), "r"(a[2]), "r"(a[3]), "r"(b[0]), "r"(b[1]));
}

__global__ void __launch_bounds__(256, 2)
cmp_mma4_kernel(const int*   __restrict__ questions,
                const float* __restrict__ qpos,
                const float* __restrict__ wemb,
                const float* __restrict__ cemb,
                const float* __restrict__ wq,
                float*       __restrict__ out)
{
    extern __shared__ float sm[];
    __shared__ int   sq[S_LEN];
    __shared__ float sp[S_LEN];
    __shared__ float sw[S_LEN];

    const int tid  = threadIdx.x;
    const int wid  = tid >> 5;
    const int lane = tid & 31;
    const int st   = blockIdx.x;           // 0..5
    const int b    = blockIdx.y;
    const int dt   = (st >= 4) ? 1 : 0;
    const int e0   = (st < 4) ? st * 64 : 128 + (st - 4) * 64;
    const bool mirror = (st == 2 || st == 3);

    if (tid < S_LEN) {
        sq[tid] = questions[b * S_LEN + tid];
        sp[tid] = qpos[b * S_LEN + tid];
        sw[tid] = wq[tid];
    }
    __syncthreads();

    const int mr = wid >> 1;       // d block (32 rows), 0..3
    const int nc = wid & 1;        // e block (32 cols), 0..1

    float accRe[2][4][4];
    float accIm[2][4][4];
#pragma unroll
    for (int i = 0; i < 2; i++)
#pragma unroll
        for (int j = 0; j < 4; j++)
#pragma unroll
            for (int q = 0; q < 4; q++) { accRe[i][j][q] = 0.f; accIm[i][j][q] = 0.f; }

    const int r = lane >> 2;
    const int c = lane & 3;

    // ---- gather chunk g into stage buffer (1536 float4 tasks / 256 thr) ----
    auto gather = [&](int g) {
        float* stage = sm + (g & 1) * STAGE_FLOATS;
        float* AR = stage;
        float* AI = stage + A_TILE;
        float* BR = stage + 2 * A_TILE;
        float* BI = stage + 2 * A_TILE + B_TILE;
#pragma unroll
        for (int i = 0; i < 6; ++i) {
            const int t = tid + i * 256;
            const bool aside = (t < 1024);
            int k, f4, fofs;
            if (aside) { k = t >> 5;  f4 = t & 31; fofs = dt * 128 + f4 * 4; }
            else { const int u = t - 1024; k = u >> 4; f4 = u & 15; fofs = e0 + f4 * 4; }

            const int   s  = g * KC + k;
            const int   q  = sq[s];
            const float pp = sp[s];
            const float4 rv = *(const float4*)(wemb + (size_t)q * D_DIM + fofs);
            const float4 cv = *(const float4*)(cemb + (size_t)q * D_DIM + fofs);
            const float ix = cv.x * pp, iy = cv.y * pp, iz = cv.z * pp, iw = cv.w * pp;

            if (aside) {
                const int dst = k * APAD + f4 * 4;
                *(uint4*)(AR + dst) = make_uint4(tf32r(rv.x), tf32r(rv.y),
                                                 tf32r(rv.z), tf32r(rv.w));
                *(uint4*)(AI + dst) = make_uint4(tf32r(ix), tf32r(iy),
                                                 tf32r(iz), tf32r(iw));
            } else {
                const float ww = sw[s];
                const int dst = k * BPAD + f4 * 4;
                *(uint4*)(BR + dst) = make_uint4(tf32r(rv.x * ww), tf32r(rv.y * ww),
                                                 tf32r(rv.z * ww), tf32r(rv.w * ww));
                *(uint4*)(BI + dst) = make_uint4(tf32r(ix * ww), tf32r(iy * ww),
                                                 tf32r(iz * ww), tf32r(iw * ww));
            }
        }
    };

    gather(0);
    __syncthreads();

    for (int g = 0; g < 4; ++g) {
        float* stage = sm + (g & 1) * STAGE_FLOATS;
        const float* AR = stage;
        const float* AI = stage + A_TILE;
        const float* BR = stage + 2 * A_TILE;
        const float* BI = stage + 2 * A_TILE + B_TILE;

        if (g < 3) gather(g + 1);   // fills other stage, overlaps compute

#pragma unroll
        for (int ks = 0; ks < 4; ++ks) {
            const int k0 = ks * 8;
            const int aL = (k0 + c) * APAD;
            const int aH = (k0 + 4 + c) * APAD;
            const int bL = (k0 + c) * BPAD;
            const int bH = (k0 + 4 + c) * BPAD;

            uint32_t bR[4][2], bI[4][2], bN[4][2];
#pragma unroll
            for (int nt = 0; nt < 4; ++nt) {
                const int n0 = nc * 32 + nt * 8 + r;
                bR[nt][0] = __float_as_uint(BR[bL + n0]);
                bR[nt][1] = __float_as_uint(BR[bH + n0]);
                bI[nt][0] = __float_as_uint(BI[bL + n0]);
                bI[nt][1] = __float_as_uint(BI[bH + n0]);
                bN[nt][0] = bI[nt][0] ^ 0x80000000u;
                bN[nt][1] = bI[nt][1] ^ 0x80000000u;
            }
#pragma unroll
            for (int mt = 0; mt < 2; ++mt) {
                const int m0 = mr * 32 + mt * 16 + r;
                uint32_t aR[4], aI[4];
                aR[0] = __float_as_uint(AR[aL + m0]);
                aR[1] = __float_as_uint(AR[aL + m0 + 8]);
                aR[2] = __float_as_uint(AR[aH + m0]);
                aR[3] = __float_as_uint(AR[aH + m0 + 8]);
                aI[0] = __float_as_uint(AI[aL + m0]);
                aI[1] = __float_as_uint(AI[aL + m0 + 8]);
                aI[2] = __float_as_uint(AI[aH + m0]);
                aI[3] = __float_as_uint(AI[aH + m0 + 8]);
#pragma unroll
                for (int nt = 0; nt < 4; ++nt) mma8(accRe[mt][nt], aR, bR[nt]);
#pragma unroll
                for (int nt = 0; nt < 4; ++nt) mma8(accRe[mt][nt], aI, bI[nt]);
#pragma unroll
                for (int nt = 0; nt < 4; ++nt) mma8(accIm[mt][nt], aI, bR[nt]);
#pragma unroll
                for (int nt = 0; nt < 4; ++nt) mma8(accIm[mt][nt], aR, bN[nt]);
            }
        }
        __syncthreads();
    }

    // ---- direct epilogue ----
    float* oRe = out + (size_t)b * D_DIM * D_DIM;
    float* oIm = oRe + (size_t)B_DIM * D_DIM * D_DIM;
#pragma unroll
    for (int mt = 0; mt < 2; ++mt) {
        const int d = dt * 128 + mr * 32 + mt * 16 + r;
#pragma unroll
        for (int nt = 0; nt < 4; ++nt) {
            const int e = e0 + nc * 32 + nt * 8 + 2 * c;
            *(float2*)(oRe + (size_t)d * D_DIM + e) =
                make_float2(accRe[mt][nt][0], accRe[mt][nt][1]);
            *(float2*)(oRe + (size_t)(d + 8) * D_DIM + e) =
                make_float2(accRe[mt][nt][2], accRe[mt][nt][3]);
            *(float2*)(oIm + (size_t)d * D_DIM + e) =
                make_float2(accIm[mt][nt][0], accIm[mt][nt][1]);
            *(float2*)(oIm + (size_t)(d + 8) * D_DIM + e) =
                make_float2(accIm[mt][nt][2], accIm[mt][nt][3]);
        }
    }

    // ---- mirror epilogue (st 2,3): write block rows e0..e0+63, cols 0..127 ----
    if (mirror) {
        float* T = sm;   // stage 0, free after main loop's final sync
#pragma unroll
        for (int mat = 0; mat < 2; ++mat) {
            __syncthreads();
            // acc -> T[e_local][d_local]
#pragma unroll
            for (int mt = 0; mt < 2; ++mt) {
                const int dl = mr * 32 + mt * 16 + r;
#pragma unroll
                for (int nt = 0; nt < 4; ++nt) {
                    const int el = nc * 32 + nt * 8 + 2 * c;
                    const float* a = mat ? accIm[mt][nt] : accRe[mt][nt];
                    T[(size_t)el * TPITCH + dl]           = a[0];
                    T[(size_t)(el + 1) * TPITCH + dl]     = a[1];
                    T[(size_t)el * TPITCH + dl + 8]       = a[2];
                    T[(size_t)(el + 1) * TPITCH + dl + 8] = a[3];
                }
            }
            __syncthreads();
            float* ob = mat ? oIm : oRe;
            const float sgn = mat ? -1.f : 1.f;
#pragma unroll
            for (int it = 0; it < 8; ++it) {
                const int el = it * 8 + wid;   // 0..63
                float4 v = *(const float4*)(T + (size_t)el * TPITCH + lane * 4);
                v.x *= sgn; v.y *= sgn; v.z *= sgn; v.w *= sgn;
                *(float4*)(ob + (size_t)(e0 + el) * D_DIM + lane * 4) = v;
            }
        }
    }
}

extern "C" void kernel_launch(void* const* d_in, const int* in_sizes, int n_in,
                              void* d_out, int out_size) {
    const int*   questions = (const int*)d_in[0];
    const float* qpos      = (const float*)d_in[1];
    const float* wemb      = (const float*)d_in[2];
    const float* cemb      = (const float*)d_in[3];
    const float* wq        = (const float*)d_in[4];
    float*       out       = (float*)d_out;

    cudaFuncSetAttribute(cmp_mma4_kernel,
                         cudaFuncAttributeMaxDynamicSharedMemorySize, SMEM_BYTES);

    dim3 grid(6 /*subtiles*/, B_DIM);
    cmp_mma4_kernel<<<grid, 256, SMEM_BYTES>>>(questions, qpos, wemb, cemb, wq, out);
}